// round 14
// baseline (speedup 1.0000x reference)
#include <cuda_runtime.h>
#include <cuda_bf16.h>

#define NLVL   4
#define BATCH  4
#define NBOX   128
#define MAXBS  64
#define CROP   14
#define CCH    256
#define NSLOTS (NLVL * BATCH * MAXBS)          // 1024
#define PTS    (CROP * CROP)                   // 196
#define C4     (CCH / 4)                       // 64 float4 per point
#define NT     (PTS / 4)                       // 49 tiles of 4 points per slot
#define GT     7                               // tiles per block
#define NGRP   (NT / GT)                       // 7 groups per slot
#define GPTS   (GT * 4)                        // 28 points per block
#define NSTG   3                               // cp.async pipeline stages

// dynamic smem: [NSTG][4 corners][256 threads] float4 = 48 KB
extern __shared__ float4 s_dyn[];

__device__ __forceinline__ void cp16(unsigned dst, const float4* src) {
    asm volatile("cp.async.cg.shared.global [%0], [%1], 16;" :: "r"(dst), "l"(src));
}

// ---------------------------------------------------------------------------
// Single fused kernel: one block per (slot, tile-group of 7).
// Warp 0 re-derives the rank->box map via ballot prefix scan; threads 0..27
// build this group's point tables; then a 3-stage cp.async pipeline over the
// 7 tiles (tile t+2 staging to smem while tile t is lerped + stored).
// Per-thread staging slots are private -> no barriers in the loop.
// ---------------------------------------------------------------------------
__global__ void __launch_bounds__(256)
roi_kernel(const float* __restrict__ f0, const float* __restrict__ f1,
           const float* __restrict__ f2, const float* __restrict__ f3,
           const float* __restrict__ db, float* __restrict__ out) {
    __shared__ int    s_map[MAXBS];  // rank -> box index
    __shared__ int    s_filled;
    __shared__ int4   s_off[GPTS];   // o00,o01,o10,o11 (float4 units)
    __shared__ float2 s_w[GPTS];     // wx, wy
    __shared__ int    s_vld[GPTS];

    int x    = blockIdx.x;                    // permuted: lvl,b fast; rank slow
    int lvl  = x & 3;
    int b    = (x >> 2) & 3;
    int rank = x >> 4;                        // 0..63
    int slotIdx = (lvl << 8) | (b << 6) | rank;

    int grp  = blockIdx.y;                    // 0..6
    int tid  = threadIdx.x;
    int pin  = tid >> 6;                      // point within tile (0..3)
    int c4   = tid & 63;
    int lane = tid & 31;

    // ---- warp 0: ballot prefix scan over this (b,lvl)'s 128 boxes ----
    if (tid < 32) {
        float flvl = (float)lvl;
        int rank_base = 0;
        #pragma unroll
        for (int k = 0; k < 4; ++k) {
            int n = k * 32 + lane;
            float id = __ldg(db + (b * NBOX + n) * 7 + 0);
            bool m = (id == flvl);
            unsigned mask = __ballot_sync(0xffffffffu, m);
            int r = rank_base + __popc(mask & ((1u << lane) - 1u));
            if (m && r < MAXBS) s_map[r] = n;
            rank_base += __popc(mask);
        }
        if (lane == 0) s_filled = rank_base < MAXBS ? rank_base : MAXBS;
    }
    __syncthreads();

    int filled = s_filled;
    int n = (rank < filled) ? s_map[rank] : -1;

    // ---- boxes output: 16 designated blocks write their (b,lvl) stripe ----
    if (grp == 0 && rank == 0) {
        float* ob_base = out + (size_t)NSLOTS * PTS * CCH
                       + ((size_t)(b * NLVL + lvl) * MAXBS) * 6;
        for (int i = tid; i < MAXBS * 6; i += 256) {
            int r = i / 6;
            int q = i - r * 6;
            float v = 0.0f;
            if (r < filled) v = __ldg(db + (b * NBOX + s_map[r]) * 7 + 1 + q);
            ob_base[i] = v;
        }
    }

    float4* base = reinterpret_cast<float4*>(out)
                 + (size_t)slotIdx * (PTS * C4) + (grp * GT * 4 + pin) * C4 + c4;
    const int TS = 4 * C4;                    // tile stride in float4

    if (n < 0) {                              // empty slot: streaming zeros
        float4 z = make_float4(0.f, 0.f, 0.f, 0.f);
        #pragma unroll
        for (int t = 0; t < GT; ++t) __stcs(base + t * TS, z);
        return;
    }

    int H = 256 >> lvl;

    if (tid < GPTS) {
        const float* bx = db + (b * NBOX + n) * 7;
        float cx = bx[1], cy = bx[2], w = bx[3], h = bx[4];

        float y1n = (cy - h * 0.5f) / 1023.0f;
        float y2n = (cy + h * 0.5f) / 1023.0f;
        float x1n = (cx - w * 0.5f) / 1023.0f;
        float x2n = (cx + w * 0.5f) / 1023.0f;

        float S = (float)(H - 1);
        int pt  = grp * GPTS + tid;           // global point index
        int py  = pt / CROP;
        int px  = pt - py * CROP;
        float ty = (float)py * (1.0f / 13.0f);
        float tx = (float)px * (1.0f / 13.0f);

        float ys = y1n * S + ty * ((y2n - y1n) * S);
        float xs = x1n * S + tx * ((x2n - x1n) * S);

        s_vld[tid] = (ys >= 0.0f && ys <= S && xs >= 0.0f && xs <= S);

        float y0f = floorf(ys), x0f = floorf(xs);
        s_w[tid] = make_float2(xs - x0f, ys - y0f);

        int y0 = (int)y0f; y0 = y0 < 0 ? 0 : (y0 > H - 1 ? H - 1 : y0);
        int yb = y0 + 1;   yb = yb > H - 1 ? H - 1 : yb;
        int x0 = (int)x0f; x0 = x0 < 0 ? 0 : (x0 > H - 1 ? H - 1 : x0);
        int xb = x0 + 1;   xb = xb > H - 1 ? H - 1 : xb;

        int rowT = (b * H + y0) * H;
        int rowB = (b * H + yb) * H;
        s_off[tid] = make_int4((rowT + x0) * C4, (rowT + xb) * C4,
                               (rowB + x0) * C4, (rowB + xb) * C4);
    }
    __syncthreads();

    const float* fm = (lvl == 0) ? f0 : (lvl == 1) ? f1 : (lvl == 2) ? f2 : f3;
    const float4* fv = reinterpret_cast<const float4*>(fm);

    // per-thread private staging slot addresses (shared address space)
    unsigned sbase = (unsigned)__cvta_generic_to_shared(&s_dyn[tid]);
    const unsigned CSTRIDE = 256 * 16;        // corner stride in bytes
    const unsigned SSTRIDE = 4 * 256 * 16;    // stage stride in bytes

    // ---- prologue: stage tiles 0 and 1 ----
    {
        int4 o = s_off[pin];
        unsigned d = sbase;                   // stage 0
        cp16(d + 0 * CSTRIDE, fv + o.x + c4);
        cp16(d + 1 * CSTRIDE, fv + o.y + c4);
        cp16(d + 2 * CSTRIDE, fv + o.z + c4);
        cp16(d + 3 * CSTRIDE, fv + o.w + c4);
    }
    asm volatile("cp.async.commit_group;" ::: "memory");
    {
        int4 o = s_off[4 + pin];
        unsigned d = sbase + SSTRIDE;         // stage 1
        cp16(d + 0 * CSTRIDE, fv + o.x + c4);
        cp16(d + 1 * CSTRIDE, fv + o.y + c4);
        cp16(d + 2 * CSTRIDE, fv + o.z + c4);
        cp16(d + 3 * CSTRIDE, fv + o.w + c4);
    }
    asm volatile("cp.async.commit_group;" ::: "memory");

    #pragma unroll
    for (int t = 0; t < GT; ++t) {
        // ---- stage tile t+2 (if any), always commit a group ----
        if (t + 2 < GT) {
            int4 o = s_off[(t + 2) * 4 + pin];
            unsigned d = sbase + ((t + 2) % NSTG) * SSTRIDE;
            cp16(d + 0 * CSTRIDE, fv + o.x + c4);
            cp16(d + 1 * CSTRIDE, fv + o.y + c4);
            cp16(d + 2 * CSTRIDE, fv + o.z + c4);
            cp16(d + 3 * CSTRIDE, fv + o.w + c4);
        }
        asm volatile("cp.async.commit_group;" ::: "memory");
        // leave at most 2 groups pending -> tile t's group is complete
        asm volatile("cp.async.wait_group 2;" ::: "memory");

        int st = t % NSTG;
        const float4* sp = &s_dyn[st * 4 * 256 + tid];
        float4 a00 = sp[0 * 256];
        float4 a01 = sp[1 * 256];
        float4 a10 = sp[2 * 256];
        float4 a11 = sp[3 * 256];

        float2 wcur = s_w[t * 4 + pin];
        int    vcur = s_vld[t * 4 + pin];

        float wx = wcur.x, wy = wcur.y;
        float ax = 1.0f - wx;
        float ay = 1.0f - wy;

        float4 r;
        r.x = (a00.x * ax + a01.x * wx) * ay + (a10.x * ax + a11.x * wx) * wy;
        r.y = (a00.y * ax + a01.y * wx) * ay + (a10.y * ax + a11.y * wx) * wy;
        r.z = (a00.z * ax + a01.z * wx) * ay + (a10.z * ax + a11.z * wx) * wy;
        r.w = (a00.w * ax + a01.w * wx) * ay + (a10.w * ax + a11.w * wx) * wy;
        if (!vcur) r = make_float4(0.f, 0.f, 0.f, 0.f);
        __stcs(base + t * TS, r);
    }
}

extern "C" void kernel_launch(void* const* d_in, const int* in_sizes, int n_in,
                              void* d_out, int out_size) {
    const float* f0 = (const float*)d_in[0];
    const float* f1 = (const float*)d_in[1];
    const float* f2 = (const float*)d_in[2];
    const float* f3 = (const float*)d_in[3];
    const float* db = (const float*)d_in[4];

    float* out = (float*)d_out;

    size_t dyn = (size_t)NSTG * 4 * 256 * sizeof(float4);   // 48 KB dynamic
    // Opt-in above the 48 KB default (static + dynamic > 48 KB otherwise
    // fails the launch). Host-side, non-stream API: graph-capture safe and
    // idempotent across calls.
    cudaFuncSetAttribute(roi_kernel, cudaFuncAttributeMaxDynamicSharedMemorySize,
                         64 * 1024);

    dim3 grid(NSLOTS, NGRP);
    roi_kernel<<<grid, 256, dyn>>>(f0, f1, f2, f3, db, out);
}

// round 15
// speedup vs baseline: 1.0998x; 1.0998x over previous
#include <cuda_runtime.h>
#include <cuda_bf16.h>

#define NLVL   4
#define BATCH  4
#define NBOX   128
#define MAXBS  64
#define CROP   14
#define CCH    256
#define NSLOTS (NLVL * BATCH * MAXBS)          // 1024
#define PTS    (CROP * CROP)                   // 196
#define C4     (CCH / 4)                       // 64 float4 per point
#define NT     (PTS / 4)                       // 49 tiles of 4 points per slot
#define GT     7                               // tiles per block
#define NGRP   (NT / GT)                       // 7 groups per slot
#define GPTS   (GT * 4)                        // 28 points per block

__device__ __forceinline__ float4 ld_corner(const float4* p, bool stream) {
    return stream ? __ldcs(p) : __ldg(p);
}

struct PointTab {
    int4   off[GPTS];
    float2 w[GPTS];
    int    vld[GPTS];
};

// 2-stage register pipeline over the 7 owned tiles. STREAM=true marks corner
// loads evict-first in L2 (used for lvl0, which can never be L2-resident).
template <bool STREAM>
__device__ __forceinline__ void mainloop(const float4* __restrict__ fv,
                                         const PointTab& tab,
                                         int pin, int c4, float4* base) {
    const int TS = 4 * C4;

    float4 a00, a01, a10, a11;
    float2 wcur;
    int    vcur;
    {
        int4 o = tab.off[pin];
        wcur = tab.w[pin];
        vcur = tab.vld[pin];
        a00 = ld_corner(fv + o.x + c4, STREAM);
        a01 = ld_corner(fv + o.y + c4, STREAM);
        a10 = ld_corner(fv + o.z + c4, STREAM);
        a11 = ld_corner(fv + o.w + c4, STREAM);
    }

    #pragma unroll
    for (int t = 0; t < GT - 1; ++t) {
        int np = (t + 1) * 4 + pin;
        int4 o = tab.off[np];
        float2 wnxt = tab.w[np];
        int    vnxt = tab.vld[np];
        float4 b00 = ld_corner(fv + o.x + c4, STREAM);
        float4 b01 = ld_corner(fv + o.y + c4, STREAM);
        float4 b10 = ld_corner(fv + o.z + c4, STREAM);
        float4 b11 = ld_corner(fv + o.w + c4, STREAM);

        float wx = wcur.x, wy = wcur.y;
        float ax = 1.0f - wx, ay = 1.0f - wy;

        float4 r;
        r.x = (a00.x * ax + a01.x * wx) * ay + (a10.x * ax + a11.x * wx) * wy;
        r.y = (a00.y * ax + a01.y * wx) * ay + (a10.y * ax + a11.y * wx) * wy;
        r.z = (a00.z * ax + a01.z * wx) * ay + (a10.z * ax + a11.z * wx) * wy;
        r.w = (a00.w * ax + a01.w * wx) * ay + (a10.w * ax + a11.w * wx) * wy;
        if (!vcur) r = make_float4(0.f, 0.f, 0.f, 0.f);
        __stcs(base + t * TS, r);

        a00 = b00; a01 = b01; a10 = b10; a11 = b11;
        wcur = wnxt; vcur = vnxt;
    }

    {
        float wx = wcur.x, wy = wcur.y;
        float ax = 1.0f - wx, ay = 1.0f - wy;

        float4 r;
        r.x = (a00.x * ax + a01.x * wx) * ay + (a10.x * ax + a11.x * wx) * wy;
        r.y = (a00.y * ax + a01.y * wx) * ay + (a10.y * ax + a11.y * wx) * wy;
        r.z = (a00.z * ax + a01.z * wx) * ay + (a10.z * ax + a11.z * wx) * wy;
        r.w = (a00.w * ax + a01.w * wx) * ay + (a10.w * ax + a11.w * wx) * wy;
        if (!vcur) r = make_float4(0.f, 0.f, 0.f, 0.f);
        __stcs(base + (GT - 1) * TS, r);
    }
}

// ---------------------------------------------------------------------------
// Single fused kernel: one block per (slot, tile-group of 7).
// Warp 0 re-derives the rank->box map via ballot prefix scan; threads 0..27
// build this group's point tables; 2-stage register pipeline over the tiles.
// ---------------------------------------------------------------------------
__global__ void __launch_bounds__(256)
roi_kernel(const float* __restrict__ f0, const float* __restrict__ f1,
           const float* __restrict__ f2, const float* __restrict__ f3,
           const float* __restrict__ db, float* __restrict__ out) {
    __shared__ int      s_map[MAXBS];  // rank -> box index
    __shared__ int      s_filled;
    __shared__ PointTab s_tab;

    int x    = blockIdx.x;                    // permuted: lvl,b fast; rank slow
    int lvl  = x & 3;
    int b    = (x >> 2) & 3;
    int rank = x >> 4;                        // 0..63
    int slotIdx = (lvl << 8) | (b << 6) | rank;

    int grp  = blockIdx.y;                    // 0..6
    int tid  = threadIdx.x;
    int pin  = tid >> 6;                      // point within tile (0..3)
    int c4   = tid & 63;
    int lane = tid & 31;

    // ---- warp 0: ballot prefix scan over this (b,lvl)'s 128 boxes ----
    if (tid < 32) {
        float flvl = (float)lvl;
        int rank_base = 0;
        #pragma unroll
        for (int k = 0; k < 4; ++k) {
            int n = k * 32 + lane;
            float id = __ldg(db + (b * NBOX + n) * 7 + 0);
            bool m = (id == flvl);
            unsigned mask = __ballot_sync(0xffffffffu, m);
            int r = rank_base + __popc(mask & ((1u << lane) - 1u));
            if (m && r < MAXBS) s_map[r] = n;
            rank_base += __popc(mask);
        }
        if (lane == 0) s_filled = rank_base < MAXBS ? rank_base : MAXBS;
    }
    __syncthreads();

    int filled = s_filled;
    int n = (rank < filled) ? s_map[rank] : -1;

    // ---- boxes output: 16 designated blocks write their (b,lvl) stripe ----
    if (grp == 0 && rank == 0) {
        float* ob_base = out + (size_t)NSLOTS * PTS * CCH
                       + ((size_t)(b * NLVL + lvl) * MAXBS) * 6;
        for (int i = tid; i < MAXBS * 6; i += 256) {
            int r = i / 6;
            int q = i - r * 6;
            float v = 0.0f;
            if (r < filled) v = __ldg(db + (b * NBOX + s_map[r]) * 7 + 1 + q);
            ob_base[i] = v;
        }
    }

    float4* base = reinterpret_cast<float4*>(out)
                 + (size_t)slotIdx * (PTS * C4) + (grp * GT * 4 + pin) * C4 + c4;
    const int TS = 4 * C4;                    // tile stride in float4

    if (n < 0) {                              // empty slot: streaming zeros
        float4 z = make_float4(0.f, 0.f, 0.f, 0.f);
        #pragma unroll
        for (int t = 0; t < GT; ++t) __stcs(base + t * TS, z);
        return;
    }

    int H = 256 >> lvl;

    if (tid < GPTS) {
        const float* bx = db + (b * NBOX + n) * 7;
        float cx = bx[1], cy = bx[2], w = bx[3], h = bx[4];

        float y1n = (cy - h * 0.5f) / 1023.0f;
        float y2n = (cy + h * 0.5f) / 1023.0f;
        float x1n = (cx - w * 0.5f) / 1023.0f;
        float x2n = (cx + w * 0.5f) / 1023.0f;

        float S = (float)(H - 1);
        int pt  = grp * GPTS + tid;           // global point index
        int py  = pt / CROP;
        int px  = pt - py * CROP;
        float ty = (float)py * (1.0f / 13.0f);
        float tx = (float)px * (1.0f / 13.0f);

        float ys = y1n * S + ty * ((y2n - y1n) * S);
        float xs = x1n * S + tx * ((x2n - x1n) * S);

        s_tab.vld[tid] = (ys >= 0.0f && ys <= S && xs >= 0.0f && xs <= S);

        float y0f = floorf(ys), x0f = floorf(xs);
        s_tab.w[tid] = make_float2(xs - x0f, ys - y0f);

        int y0 = (int)y0f; y0 = y0 < 0 ? 0 : (y0 > H - 1 ? H - 1 : y0);
        int yb = y0 + 1;   yb = yb > H - 1 ? H - 1 : yb;
        int x0 = (int)x0f; x0 = x0 < 0 ? 0 : (x0 > H - 1 ? H - 1 : x0);
        int xb = x0 + 1;   xb = xb > H - 1 ? H - 1 : xb;

        int rowT = (b * H + y0) * H;
        int rowB = (b * H + yb) * H;
        s_tab.off[tid] = make_int4((rowT + x0) * C4, (rowT + xb) * C4,
                                   (rowB + x0) * C4, (rowB + xb) * C4);
    }
    __syncthreads();

    const float* fm = (lvl == 0) ? f0 : (lvl == 1) ? f1 : (lvl == 2) ? f2 : f3;
    const float4* fv = reinterpret_cast<const float4*>(fm);

    if (lvl == 0) mainloop<true >(fv, s_tab, pin, c4, base);   // evict-first
    else          mainloop<false>(fv, s_tab, pin, c4, base);   // default cache
}

extern "C" void kernel_launch(void* const* d_in, const int* in_sizes, int n_in,
                              void* d_out, int out_size) {
    const float* f0 = (const float*)d_in[0];
    const float* f1 = (const float*)d_in[1];
    const float* f2 = (const float*)d_in[2];
    const float* f3 = (const float*)d_in[3];
    const float* db = (const float*)d_in[4];

    float* out = (float*)d_out;

    dim3 grid(NSLOTS, NGRP);
    roi_kernel<<<grid, 256>>>(f0, f1, f2, f3, db, out);
}